// round 1
// baseline (speedup 1.0000x reference)
#include <cuda_runtime.h>
#include <math.h>

#define NE 64
#define NH 512
#define NF 2048
#define NT 2048

// 16 MB scratch for intermediate h = gelu(x @ w1^T), plus expert offsets.
__device__ float g_h[(size_t)NT * NF];
__device__ int g_offs[NE + 1];

// ---------------------------------------------------------------------------
// Offsets: exclusive prefix sum of tokens_per_expert (tiny).
// ---------------------------------------------------------------------------
__global__ void offs_kernel(const int* __restrict__ counts) {
    __shared__ int s[NE];
    int tid = threadIdx.x;
    if (tid < NE) s[tid] = counts[tid];
    __syncthreads();
    if (tid == 0) {
        int acc = 0;
        g_offs[0] = 0;
        #pragma unroll
        for (int e = 0; e < NE; ++e) { acc += s[e]; g_offs[e + 1] = acc; }
    }
}

__device__ __forceinline__ float gelu_exact(float v) {
    return 0.5f * v * (1.0f + erff(v * 0.7071067811865476f));
}

// ---------------------------------------------------------------------------
// GEMM1 + GELU:  h[t, f] = gelu( sum_k x[t,k] * w1[e,f,k] )
// Tile: M=32 tokens, N=128 f-rows, K=32. Block = 256 threads.
// Warp = 4-token group (A reads are warp-uniform broadcasts), lane = 4-f group.
// xs is stored K-major (transposed) so the A read is one broadcast float4.
// ws is stored K-major (transposed from w1's f-major rows).
// ---------------------------------------------------------------------------
__global__ __launch_bounds__(256) void gemm1_kernel(
    const float* __restrict__ x, const float* __restrict__ w1)
{
    __shared__ float xs[32][36];    // [k][m], pad 4 keeps float4 row alignment
    __shared__ float ws[32][132];   // [k][n], 132*4B = 528B rows, 16B aligned

    const int e  = blockIdx.y;
    const int f0 = blockIdx.x * 128;
    const int base = g_offs[e];
    const int cnt  = g_offs[e + 1] - base;
    const int tid = threadIdx.x;
    const int mt = tid >> 5;   // warp id -> token group (4 tokens)
    const int nt = tid & 31;   // lane    -> f group (4 f)
    const float* w1e = w1 + (size_t)e * NF * NH;

    for (int m0 = 0; m0 < cnt; m0 += 32) {
        float c[4][4];
        #pragma unroll
        for (int i = 0; i < 4; ++i)
            #pragma unroll
            for (int j = 0; j < 4; ++j) c[i][j] = 0.0f;

        for (int k0 = 0; k0 < NH; k0 += 32) {
            // ---- stage x tile (transposed: xs[k][m]) ----
            {
                const int m  = tid >> 3;
                const int k4 = (tid & 7) * 4;
                float4 v = make_float4(0.f, 0.f, 0.f, 0.f);
                if (m0 + m < cnt)
                    v = *(const float4*)&x[(size_t)(base + m0 + m) * NH + k0 + k4];
                xs[k4 + 0][m] = v.x; xs[k4 + 1][m] = v.y;
                xs[k4 + 2][m] = v.z; xs[k4 + 3][m] = v.w;
            }
            // ---- stage w1 tile (transposed: ws[k][n]), 128 rows in 4 passes ----
            #pragma unroll
            for (int nn = 0; nn < 4; ++nn) {
                const int n  = nn * 32 + (tid >> 3);
                const int k4 = (tid & 7) * 4;
                float4 v = *(const float4*)&w1e[(size_t)(f0 + n) * NH + k0 + k4];
                ws[k4 + 0][n] = v.x; ws[k4 + 1][n] = v.y;
                ws[k4 + 2][n] = v.z; ws[k4 + 3][n] = v.w;
            }
            __syncthreads();

            #pragma unroll 8
            for (int kk = 0; kk < 32; ++kk) {
                float a[4], b[4];
                *(float4*)a = *(const float4*)&xs[kk][mt * 4];  // broadcast
                *(float4*)b = *(const float4*)&ws[kk][nt * 4];
                #pragma unroll
                for (int i = 0; i < 4; ++i)
                    #pragma unroll
                    for (int j = 0; j < 4; ++j)
                        c[i][j] = fmaf(a[i], b[j], c[i][j]);
            }
            __syncthreads();
        }

        // ---- epilogue: GELU, store to scratch ----
        #pragma unroll
        for (int i = 0; i < 4; ++i) {
            const int m = m0 + mt * 4 + i;
            if (m < cnt) {
                float4 o;
                o.x = gelu_exact(c[i][0]);
                o.y = gelu_exact(c[i][1]);
                o.z = gelu_exact(c[i][2]);
                o.w = gelu_exact(c[i][3]);
                *(float4*)&g_h[(size_t)(base + m) * NF + f0 + nt * 4] = o;
            }
        }
    }
}

// ---------------------------------------------------------------------------
// GEMM2:  out[t, n] = sum_k h[t,k] * w2[e,k,n]     (K = 2048, N = 512)
// Tile: M=32 tokens, N=64, K=32. Block = 256 threads, thread tile 4x2.
// w2 rows are already n-contiguous -> no transpose needed for ws2.
// ---------------------------------------------------------------------------
__global__ __launch_bounds__(256) void gemm2_kernel(
    const float* __restrict__ w2, float* __restrict__ out)
{
    __shared__ float hs[32][36];   // [k][m] transposed
    __shared__ float ws2[32][68];  // [k][n], 68*4B = 272B rows, 16B aligned

    const int e  = blockIdx.y;
    const int n0 = blockIdx.x * 64;
    const int base = g_offs[e];
    const int cnt  = g_offs[e + 1] - base;
    const int tid = threadIdx.x;
    const int mt = tid >> 5;
    const int nt = tid & 31;
    const float* w2e = w2 + (size_t)e * NF * NH;

    for (int m0 = 0; m0 < cnt; m0 += 32) {
        float c[4][2];
        #pragma unroll
        for (int i = 0; i < 4; ++i) { c[i][0] = 0.0f; c[i][1] = 0.0f; }

        for (int k0 = 0; k0 < NF; k0 += 32) {
            // ---- stage h tile (transposed: hs[k][m]) ----
            {
                const int m  = tid >> 3;
                const int k4 = (tid & 7) * 4;
                float4 v = make_float4(0.f, 0.f, 0.f, 0.f);
                if (m0 + m < cnt)
                    v = *(const float4*)&g_h[(size_t)(base + m0 + m) * NF + k0 + k4];
                hs[k4 + 0][m] = v.x; hs[k4 + 1][m] = v.y;
                hs[k4 + 2][m] = v.z; hs[k4 + 3][m] = v.w;
            }
            // ---- stage w2 tile (direct: ws2[k][n]) ----
            {
                const int kk = tid >> 3;
                const int nq = (tid & 7) * 4;
                const float* src = &w2e[(size_t)(k0 + kk) * NH + n0];
                *(float4*)&ws2[kk][nq]      = *(const float4*)&src[nq];
                *(float4*)&ws2[kk][nq + 32] = *(const float4*)&src[nq + 32];
            }
            __syncthreads();

            #pragma unroll 8
            for (int kk = 0; kk < 32; ++kk) {
                float a[4], b[2];
                *(float4*)a = *(const float4*)&hs[kk][mt * 4];  // broadcast
                *(float2*)b = *(const float2*)&ws2[kk][nt * 2];
                #pragma unroll
                for (int i = 0; i < 4; ++i) {
                    c[i][0] = fmaf(a[i], b[0], c[i][0]);
                    c[i][1] = fmaf(a[i], b[1], c[i][1]);
                }
            }
            __syncthreads();
        }

        #pragma unroll
        for (int i = 0; i < 4; ++i) {
            const int m = m0 + mt * 4 + i;
            if (m < cnt) {
                float2 o; o.x = c[i][0]; o.y = c[i][1];
                *(float2*)&out[(size_t)(base + m) * NH + n0 + nt * 2] = o;
            }
        }
    }
}

// ---------------------------------------------------------------------------
extern "C" void kernel_launch(void* const* d_in, const int* in_sizes, int n_in,
                              void* d_out, int out_size) {
    const float* x  = (const float*)d_in[0];
    const float* w1 = (const float*)d_in[1];
    const float* w2 = (const float*)d_in[2];
    const int* tokens_per_expert = (const int*)d_in[3];
    float* out = (float*)d_out;

    offs_kernel<<<1, 64>>>(tokens_per_expert);
    gemm1_kernel<<<dim3(NF / 128, NE), 256>>>(x, w1);
    gemm2_kernel<<<dim3(NH / 64, NE), 256>>>(w2, out);
}